// round 16
// baseline (speedup 1.0000x reference)
#include <cuda_runtime.h>
#include <cuda_bf16.h>
#include <cuda_fp16.h>
#include <float.h>
#include <math.h>
#include <stdint.h>

// Problem constants (fixed shapes)
#define BN_TOT 64      // b*r
#define NB 2           // b
#define RR 32          // r
#define NN 512         // n
#define DIMC 256       // DIM
#define HH 8           // heads
#define DH 64          // dim_head
#define INNERD 512     // HH*DH
#define KW 15          // conv kernel

// ---------------- scratch (device globals; no allocations allowed) ----------
__device__ float g_dots[NB * HH * NN * NN];         // logits fp32

// fp16 hi-only operands everywhere
__device__ uint16_t g_xs_h[BN_TOT * NN * DIMC];
__device__ uint16_t g_hdw_h[BN_TOT * NN * DIMC];
__device__ uint16_t g_pww_h[INNERD * DIMC];
__device__ uint16_t g_wkvT_h[2 * INNERD * DIMC];
__device__ uint16_t g_woT_h[DIMC * INNERD];
__device__ uint16_t g_vT_h[BN_TOT * INNERD * NN];
__device__ uint16_t g_attn_h[NB * HH * NN * NN];
__device__ uint16_t g_oi_h[BN_TOT * NN * INNERD];
__device__ uint16_t g_qr_h[NB * HH * NN * RR * DH];
__device__ uint16_t g_kr_h[NB * HH * NN * RR * DH];

__device__ unsigned char g_mask[BN_TOT * NN];
__device__ float g_has_rows[BN_TOT];
__device__ float g_m_any[NB * NN];
__device__ float g_alpha[NB];
__device__ float g_sin[NN * 32];
__device__ float g_cos[NN * 32];

// ========================= helpers ===========================================
__device__ __forceinline__ uint32_t smem_u32(const void* p) {
    uint32_t a;
    asm("{ .reg .u64 t; cvta.to.shared.u64 t, %1; cvt.u32.u64 %0, t; }" : "=r"(a) : "l"(p));
    return a;
}

#define LDSM4(r, addr)                                                          \
    asm volatile("ldmatrix.sync.aligned.m8n8.x4.shared.b16 {%0,%1,%2,%3}, [%4];" \
                 : "=r"((r)[0]), "=r"((r)[1]), "=r"((r)[2]), "=r"((r)[3])       \
                 : "r"(addr))

__device__ __forceinline__ void mma_h(float* c, const uint32_t* a, const uint32_t* b) {
    asm volatile("mma.sync.aligned.m16n8k16.row.col.f32.f16.f16.f32 "
                 "{%0,%1,%2,%3}, {%4,%5,%6,%7}, {%8,%9}, {%0,%1,%2,%3};"
                 : "+f"(c[0]), "+f"(c[1]), "+f"(c[2]), "+f"(c[3])
                 : "r"(a[0]), "r"(a[1]), "r"(a[2]), "r"(a[3]), "r"(b[0]), "r"(b[1]));
}

#define CP16(dst, src)                                                          \
    asm volatile("cp.async.cg.shared.global [%0], [%1], 16;" :: "r"(dst), "l"(src) : "memory")
#define CP_COMMIT() asm volatile("cp.async.commit_group;" ::: "memory")
#define CP_WAIT0()  asm volatile("cp.async.wait_group 0;" ::: "memory")

// byte offset in a 128B-per-row fp16 tile (64 k values/row), bank-swizzled
__device__ __forceinline__ uint32_t soff(int row, int kcol) {
    return (uint32_t)(row * 128 + ((kcol * 2) ^ ((row & 7) << 4)));
}

__device__ __forceinline__ uint16_t h16(float v) {
    return __half_as_ushort(__float2half_rn(v));
}

// ========================= fused prep (mask + trig), ONE block ===============
__global__ void __launch_bounds__(1024) k_prep(const void* mraw) {
    const unsigned char* mb = (const unsigned char*)mraw;
    int tid = threadIdx.x;
    __shared__ int s_high, s_odd;

    if (tid == 0) { s_high = 0; s_odd = 0; }
    __syncthreads();
    for (int idx = tid; idx < BN_TOT * NN; idx += 1024) {
        unsigned char v = mb[idx];
        if (v > 1) s_high = 1;
        if ((idx & 3) && v) s_odd = 1;
    }
    __syncthreads();
    int mode = s_high ? 2 : (s_odd ? 0 : 1);

    for (int idx = tid; idx < BN_TOT * NN; idx += 1024) {
        unsigned char v;
        if (mode == 0)      v = (mb[idx] != 0);
        else if (mode == 1) v = (((const int*)mraw)[idx] != 0);
        else                v = (((const float*)mraw)[idx] != 0.0f);
        g_mask[idx] = v;
    }
    __syncthreads();

    int w = tid >> 5, lane = tid & 31;
    for (int bb = 0; bb < 2; bb++) {
        int bn = w * 2 + bb;
        int any = 0;
        for (int q = lane; q < NN; q += 32) any |= g_mask[bn * NN + q];
        any = __any_sync(0xFFFFFFFFu, any);
        if (lane == 0) g_has_rows[bn] = (float)any;
    }
    __syncthreads();

    {
        int b = tid >> 9, i = tid & 511;
        int any = 0;
        for (int r = 0; r < RR; r++) any |= g_mask[(b * RR + r) * NN + i];
        g_m_any[b * NN + i] = (float)any;
        if (i == 0) {
            float s = 0.f;
            for (int r = 0; r < RR; r++) s += g_has_rows[b * RR + r];
            g_alpha[b] = (s > 0.f) ? 0.125f * rsqrtf(s) : 0.f;
        }
    }

    for (int idx = tid; idx < NN * 32; idx += 1024) {
        int i = idx >> 5, j = idx & 31;
        float inv = exp2f(-((float)(2 * j) / 64.0f) * 13.287712379549449f);
        float ang = (float)i * inv;
        g_sin[idx] = sinf(ang);
        g_cos[idx] = cosf(ang);
    }
}

// ========================= fused weight transforms ===========================
__global__ void k_wprep(const float* __restrict__ pw_w,
                        const float* __restrict__ w_kv,
                        const float* __restrict__ w_o) {
    int bid = blockIdx.x;
    int t = threadIdx.x;
    if (bid < 512) {
        int i = bid * 256 + t;
        g_pww_h[i] = h16(pw_w[i]);
    } else if (bid < 1536) {
        int i = (bid - 512) * 256 + t;
        int n = i >> 8, k = i & 255;
        g_wkvT_h[i] = h16(w_kv[k * 1024 + n]);
    } else {
        int i = (bid - 1536) * 256 + t;
        int n = i >> 9, k = i & 511;
        g_woT_h[i] = h16(w_o[k * 256 + n]);
    }
}

// ---------------- depthwise conv (also emits xs_h for free) ------------------
__global__ void __launch_bounds__(256) k_conv2(const float* __restrict__ x,
                                               const float* __restrict__ dww,
                                               const float* __restrict__ dwb) {
    int c = threadIdx.x;
    int bn = blockIdx.y, seg = blockIdx.x;
    int i0 = seg * 128;
    float w[KW];
#pragma unroll
    for (int k = 0; k < KW; k++) w[k] = dww[c * KW + k];
    float bias = dwb[c];
    const float* xr = x + (size_t)bn * NN * DIMC + c;

    float win[KW];
#pragma unroll
    for (int k = 0; k < KW; k++) {
        int ii = i0 - KW / 2 + k;
        win[k] = (ii >= 0 && ii < NN) ? xr[(size_t)ii * DIMC] : 0.f;
    }
    uint16_t* oh = g_hdw_h + ((size_t)bn * NN + i0) * DIMC + c;
    uint16_t* ox = g_xs_h + ((size_t)bn * NN + i0) * DIMC + c;
    for (int i = i0; i < i0 + 128; i++) {
        float acc = bias;
#pragma unroll
        for (int k = 0; k < KW; k++) acc = fmaf(win[k], w[k], acc);
        *oh = h16(acc);
        *ox = h16(win[KW / 2]);
        oh += DIMC; ox += DIMC;
#pragma unroll
        for (int k = 0; k < KW - 1; k++) win[k] = win[k + 1];
        int ii = i + KW / 2 + 1;
        win[KW - 1] = (ii < NN) ? xr[(size_t)ii * DIMC] : 0.f;
    }
}

// ---------------- masked softmax (writes fp16 hi) ----------------------------
__global__ void k_softmax() {
    int row = blockIdx.x;
    int b = row >> 12;
    int i = row & 511;
    const float* p = g_dots + (size_t)row * NN;
    float rv = g_m_any[b * NN + i];
    int t = threadIdx.x;

    float m0 = g_m_any[b * NN + t];
    float m1 = g_m_any[b * NN + t + 256];
    float x0 = (rv != 0.f && m0 != 0.f) ? p[t]       : -FLT_MAX;
    float x1 = (rv != 0.f && m1 != 0.f) ? p[t + 256] : -FLT_MAX;

    __shared__ float red[256];
    float mx = fmaxf(x0, x1);
    red[t] = mx;
    __syncthreads();
    for (int s = 128; s > 0; s >>= 1) {
        if (t < s) red[t] = fmaxf(red[t], red[t + s]);
        __syncthreads();
    }
    mx = red[0];
    __syncthreads();
    float e0 = expf(x0 - mx), e1 = expf(x1 - mx);
    red[t] = e0 + e1;
    __syncthreads();
    for (int s = 128; s > 0; s >>= 1) {
        if (t < s) red[t] += red[t + s];
        __syncthreads();
    }
    float inv = 1.0f / red[0];
    size_t o = (size_t)row * NN;
    g_attn_h[o + t]       = h16(e0 * inv);
    g_attn_h[o + t + 256] = h16(e1 * inv);
}

// rotary epilogue: write fp16 hi-only q/k in (b,h,i,r*64+d) layout
__device__ __forceinline__ void rot_store(int row, int col, float ve, float vo,
                                          bool isq) {
    int i = row & 511, bn = row >> 9;
    int h = col >> 6, d = col & 63, j = d >> 1;
    float s = g_sin[i * 32 + j], c = g_cos[i * 32 + j];
    float oe = ve * c - vo * s;
    float oo = vo * c + ve * s;
    int b = bn >> 5, r = bn & 31;
    size_t dst = (((size_t)(b * HH + h) * NN + i) * (RR * DH)) + r * DH + d;
    if (isq) {
        float hr = g_has_rows[bn];
        oe *= hr; oo *= hr;
        *(uint32_t*)(g_qr_h + dst) = (uint32_t)h16(oe) | ((uint32_t)h16(oo) << 16);
    } else {
        *(uint32_t*)(g_kr_h + dst) = (uint32_t)h16(oe) | ((uint32_t)h16(oo) << 16);
    }
}

// ======= projection GEMM: B panel resident (K=256), 4 M-tiles per CTA ========
// grid (12, 64): bx<4 q (hdw @ pww), 4..7 k (x @ wkvT[0:512]), 8..11 v.
// Each CTA: load 64KB B panel once, then loop 4 M-tiles streaming A.
__global__ void __launch_bounds__(256, 2) k_proj(const float* __restrict__ pwb) {
    extern __shared__ __align__(128) char dsm[];
    uint32_t sb = smem_u32(dsm);
    uint32_t aBase = sb + 65536;           // A stages after 64KB B panel

    int tid = threadIdx.x, wid = tid >> 5, lane = tid & 31;
    int bx = blockIdx.x;

    const uint16_t* Asrc;
    const uint16_t* Bsrc;
    if (bx < 4)      { Asrc = g_hdw_h; Bsrc = g_pww_h + (size_t)bx * 128 * DIMC; }
    else if (bx < 8) { Asrc = g_xs_h;  Bsrc = g_wkvT_h + (size_t)(bx - 4) * 128 * DIMC; }
    else             { Asrc = g_xs_h;  Bsrc = g_wkvT_h + (size_t)(512 + (bx - 8) * 128) * DIMC; }

    // load full B panel: 4 chunks x (128 rows x 64 k)
    for (int idx = tid; idx < 4096; idx += 256) {
        int ch = idx >> 10, r = (idx >> 3) & 127, c = idx & 7;
        uint32_t off = (uint32_t)(ch * 16384 + r * 128 + ((c * 16) ^ ((r & 7) << 4)));
        CP16(sb + off, Bsrc + (size_t)r * DIMC + ch * 64 + c * 8);
    }
    CP_COMMIT();

    int m0 = (wid & 1) * 64;
    int n0 = (wid >> 1) * 32;
    int arow = m0 + (lane & 7) + ((lane >> 3) & 1) * 8;
    int akb  = ((lane >> 4) & 1) * 8;
    int brow = n0 + (lane & 7) + ((lane >> 4) & 1) * 8;
    int bkb  = ((lane >> 3) & 1) * 8;

    for (int jt = 0; jt < 4; jt++) {
        int by = blockIdx.y * 4 + jt;
        const uint16_t* Ah = Asrc + (size_t)by * 128 * DIMC;

        float acc[4][4][4];
#pragma unroll
        for (int i = 0; i < 4; i++)
#pragma unroll
            for (int j = 0; j < 4; j++)
#pragma unroll
                for (int q = 0; q < 4; q++) acc[i][j][q] = 0.f;

        // A chunk 0
        for (int idx = tid; idx < 1024; idx += 256) {
            int r = idx >> 3, c = idx & 7;
            uint32_t off = (uint32_t)(r * 128 + ((c * 16) ^ ((r & 7) << 4)));
            CP16(aBase + off, Ah + (size_t)r * DIMC + c * 8);
        }
        CP_COMMIT();

        for (int ch = 0; ch < 4; ch++) {
            CP_WAIT0();
            __syncthreads();
            if (ch + 1 < 4) {
                uint32_t st = aBase + (uint32_t)((ch + 1) & 1) * 16384;
                int k0 = (ch + 1) << 6;
                for (int idx = tid; idx < 1024; idx += 256) {
                    int r = idx >> 3, c = idx & 7;
                    uint32_t off = (uint32_t)(r * 128 + ((c * 16) ^ ((r & 7) << 4)));
                    CP16(st + off, Ah + (size_t)r * DIMC + k0 + c * 8);
                }
                CP_COMMIT();
            }

            uint32_t aHiB = aBase + (uint32_t)(ch & 1) * 16384;
            uint32_t bHiB = sb + (uint32_t)ch * 16384;

#pragma unroll
            for (int kk = 0; kk < 64; kk += 16) {
                uint32_t ah[4][4];
#pragma unroll
                for (int mt = 0; mt < 4; mt++)
                    LDSM4(ah[mt], aHiB + soff(arow + mt * 16, kk + akb));
                uint32_t bh[2][4];
#pragma unroll
                for (int nx = 0; nx < 2; nx++)
                    LDSM4(bh[nx], bHiB + soff(brow + nx * 16, kk + bkb));
#pragma unroll
                for (int mt = 0; mt < 4; mt++)
#pragma unroll
                    for (int nt = 0; nt < 4; nt++)
                        mma_h(acc[mt][nt], ah[mt], &bh[nt >> 1][(nt & 1) * 2]);
            }
        }

        // ---- epilogue for this M-tile ----
        int r0 = by * 128 + m0 + (lane >> 2);
        if (bx >= 8) {
            // V: transpose 128x128 tile through smem scratch (at aBase) -> vT_h
            __syncthreads();
            uint16_t* sm = (uint16_t*)(dsm + 65536);   // 128*132*2 = 33792 B
            int rl0 = m0 + (lane >> 2);
            int cl0 = n0 + (lane & 3) * 2;
#pragma unroll
            for (int mt = 0; mt < 4; mt++)
#pragma unroll
                for (int nt = 0; nt < 4; nt++) {
                    int rl = rl0 + mt * 16, cl = cl0 + nt * 8;
                    sm[(cl + 0) * 132 + rl]     = h16(acc[mt][nt][0]);
                    sm[(cl + 1) * 132 + rl]     = h16(acc[mt][nt][1]);
                    sm[(cl + 0) * 132 + rl + 8] = h16(acc[mt][nt][2]);
                    sm[(cl + 1) * 132 + rl + 8] = h16(acc[mt][nt][3]);
                }
            __syncthreads();
            int bn = by >> 2, i0g = (by & 3) * 128;
            int hd0 = (bx - 8) * 128;
            int c = tid >> 1, half = tid & 1;
            size_t dst = ((size_t)bn * 512 + hd0 + c) * 512 + i0g + half * 64;
            const uint16_t* srow = sm + c * 132 + half * 64;
#pragma unroll 4
            for (int r = 0; r < 64; r += 4) {
                uint2 val;
                val.x = (uint32_t)srow[r]     | ((uint32_t)srow[r + 1] << 16);
                val.y = (uint32_t)srow[r + 2] | ((uint32_t)srow[r + 3] << 16);
                *(uint2*)(g_vT_h + dst + r) = val;
            }
            __syncthreads();               // scratch reuse before next tile's A loads
        } else {
            bool isq = (bx < 4);
            int c0l = (bx & 3) * 128 + n0 + (lane & 3) * 2;
#pragma unroll
            for (int mt = 0; mt < 4; mt++)
#pragma unroll
                for (int nt = 0; nt < 4; nt++) {
                    int row = r0 + mt * 16;
                    int col = c0l + nt * 8;
                    float b0 = 0.f, b1 = 0.f;
                    if (isq) { b0 = pwb[col]; b1 = pwb[col + 1]; }
                    rot_store(row, col, acc[mt][nt][0] + b0, acc[mt][nt][1] + b1, isq);
                    rot_store(row + 8, col, acc[mt][nt][2] + b0, acc[mt][nt][3] + b1, isq);
                }
            __syncthreads();               // stage reuse before next tile's A loads
        }
    }
}

// ======= generic mma.sync fp16 NT GEMM, BK=64, 2-stage (R13 structure) =======
struct GemmP {
    const uint16_t *Ah; long long lda; long long a_bs;
    const uint16_t *Bh; long long ldb; long long b_bs;
    float* C;                                  // fp32 out (or null)
    uint16_t *Ch;                              // fp16 hi out (or null)
    long long ldc; long long c_bs;
    int K;
    const float* bias;
    const float* alpha_vec; int alpha_shift;
    int mode;   // 0 normal batch, 1 = AV addressing
};

template <int TN>
__global__ void __launch_bounds__(256) k_mma(GemmP p) {
    constexpr int NT8 = TN / 32;
    constexpr int NX4 = NT8 / 2;
    constexpr uint32_t SS = 16384u + TN * 128u;    // stage stride bytes (BK=64)
    extern __shared__ __align__(128) char dsm[];
    uint32_t sb = smem_u32(dsm);

    int tid = threadIdx.x, wid = tid >> 5, lane = tid & 31;
    int bx = blockIdx.x, by = blockIdx.y, z = blockIdx.z;

    size_t abase, cbase;
    size_t bbase = (size_t)z * p.b_bs + (size_t)bx * TN * p.ldb;
    if (p.mode == 0) {
        abase = (size_t)z * p.a_bs;
        cbase = (size_t)z * p.c_bs;
    } else {                                  // AV: z = bn*8 + h
        int bn = z >> 3, h = z & 7, b = bn >> 5;
        abase = (size_t)(b * HH + h) * p.a_bs;
        cbase = (size_t)bn * p.c_bs + h * 64;
    }
    abase += (size_t)by * 128 * p.lda;
    const uint16_t* Ah = p.Ah + abase;
    const uint16_t* Bh = p.Bh + bbase;

    int m0 = (wid & 1) * 64;
    int n0 = (wid >> 1) * (TN / 4);
    int arow = m0 + (lane & 7) + ((lane >> 3) & 1) * 8;
    int akb  = ((lane >> 4) & 1) * 8;
    int brow = n0 + (lane & 7) + ((lane >> 4) & 1) * 8;
    int bkb  = ((lane >> 3) & 1) * 8;

    float acc[4][NT8][4];
#pragma unroll
    for (int i = 0; i < 4; i++)
#pragma unroll
        for (int j = 0; j < NT8; j++)
#pragma unroll
            for (int q = 0; q < 4; q++) acc[i][j][q] = 0.f;

    int KC = p.K >> 6;                     // BK = 64

    auto load_stage = [&](int st, int k0) {
        uint32_t base = sb + (uint32_t)st * SS;
#pragma unroll 4
        for (int idx = tid; idx < 1024; idx += 256) {
            int row = idx >> 3, c = idx & 7;
            uint32_t off = (uint32_t)(row * 128 + ((c * 16) ^ ((row & 7) << 4)));
            CP16(base + off, Ah + (size_t)row * p.lda + k0 + c * 8);
        }
#pragma unroll 4
        for (int idx = tid; idx < TN * 8; idx += 256) {
            int row = idx >> 3, c = idx & 7;
            uint32_t off = (uint32_t)(row * 128 + ((c * 16) ^ ((row & 7) << 4)));
            CP16(base + 16384 + off, Bh + (size_t)row * p.ldb + k0 + c * 8);
        }
    };

    load_stage(0, 0);
    CP_COMMIT();

    for (int ch = 0; ch < KC; ch++) {
        CP_WAIT0();
        __syncthreads();
        if (ch + 1 < KC) {
            load_stage((ch + 1) & 1, (ch + 1) << 6);
            CP_COMMIT();
        }

        uint32_t base = sb + (uint32_t)(ch & 1) * SS;
        uint32_t aHiB = base, bHiB = base + 16384;

#pragma unroll
        for (int kk = 0; kk < 64; kk += 16) {
            uint32_t ah[4][4];
#pragma unroll
            for (int mt = 0; mt < 4; mt++)
                LDSM4(ah[mt], aHiB + soff(arow + mt * 16, kk + akb));
            uint32_t bh[NX4][4];
#pragma unroll
            for (int nx = 0; nx < NX4; nx++)
                LDSM4(bh[nx], bHiB + soff(brow + nx * 16, kk + bkb));
#pragma unroll
            for (int mt = 0; mt < 4; mt++)
#pragma unroll
                for (int nt = 0; nt < NT8; nt++)
                    mma_h(acc[mt][nt], ah[mt], &bh[nt >> 1][(nt & 1) * 2]);
        }
    }

    // epilogue
    float alpha = p.alpha_vec ? p.alpha_vec[z >> p.alpha_shift] : 1.0f;
    int r0 = by * 128 + m0 + (lane >> 2);
    int c0 = bx * TN + n0 + (lane & 3) * 2;
#pragma unroll
    for (int mt = 0; mt < 4; mt++) {
#pragma unroll
        for (int nt = 0; nt < NT8; nt++) {
            int row = r0 + mt * 16;
            int col = c0 + nt * 8;
            float b0 = 0.f, b1 = 0.f;
            if (p.bias) { b0 = p.bias[col]; b1 = p.bias[col + 1]; }
            float v00 = acc[mt][nt][0] * alpha + b0;
            float v01 = acc[mt][nt][1] * alpha + b1;
            float v10 = acc[mt][nt][2] * alpha + b0;
            float v11 = acc[mt][nt][3] * alpha + b1;
            if (p.C) {
                *(float2*)(p.C + cbase + (size_t)row * p.ldc + col) = make_float2(v00, v01);
                *(float2*)(p.C + cbase + (size_t)(row + 8) * p.ldc + col) = make_float2(v10, v11);
            }
            if (p.Ch) {
                *(uint32_t*)(p.Ch + cbase + (size_t)row * p.ldc + col) =
                    (uint32_t)h16(v00) | ((uint32_t)h16(v01) << 16);
                *(uint32_t*)(p.Ch + cbase + (size_t)(row + 8) * p.ldc + col) =
                    (uint32_t)h16(v10) | ((uint32_t)h16(v11) << 16);
            }
        }
    }
}

// ---------------- launch -----------------------------------------------------
#define SYM(var, sym) decltype(&sym[0]) var; cudaGetSymbolAddress((void**)&var, sym)

extern "C" void kernel_launch(void* const* d_in, const int* in_sizes, int n_in,
                              void* d_out, int out_size) {
    const float* x    = (const float*)d_in[0];
    const void*  mask = d_in[1];
    const float* dw_w = (const float*)d_in[3];
    const float* dw_b = (const float*)d_in[4];
    const float* pw_w = (const float*)d_in[5];
    const float* pw_b = (const float*)d_in[6];
    const float* w_kv = (const float*)d_in[7];
    const float* w_o  = (const float*)d_in[8];
    const float* b_o  = (const float*)d_in[9];
    float* out = (float*)d_out;

    const int SMPROJ = 65536 + 33792;            // B panel + max(A stages, scratch)
    const int SM128 = 2 * (16384 + 128 * 128);   // 65536
    const int SM64  = 2 * (16384 + 64 * 128);    // 49152
    cudaFuncSetAttribute(k_proj,     cudaFuncAttributeMaxDynamicSharedMemorySize, SMPROJ);
    cudaFuncSetAttribute(k_mma<128>, cudaFuncAttributeMaxDynamicSharedMemorySize, SM128);
    cudaFuncSetAttribute(k_mma<64>,  cudaFuncAttributeMaxDynamicSharedMemorySize, SM64);

    SYM(dots_p, g_dots);
    SYM(qr_h, g_qr_h);
    SYM(kr_h, g_kr_h);
    SYM(attn_h, g_attn_h);
    SYM(vT_h, g_vT_h);
    SYM(oi_h, g_oi_h);
    SYM(woT_h, g_woT_h);
    SYM(alpha_p, g_alpha);

    k_prep<<<1, 1024>>>(mask);
    k_wprep<<<2048, 256>>>(pw_w, w_kv, w_o);
    k_conv2<<<dim3(4, BN_TOT), 256>>>(x, dw_w, dw_b);

    // merged projections, B-panel resident: q / k / v
    k_proj<<<dim3(12, 64), 256, SMPROJ>>>(pw_b);

    // dots: 16 batches, M=N=512, K=2048 -> fp32 (alpha per b)
    {
        GemmP p = {qr_h, 2048, (long long)NN * 2048, kr_h, 2048, (long long)NN * 2048,
                   dots_p, nullptr, NN, (long long)NN * NN,
                   2048, nullptr, alpha_p, 3, 0};
        k_mma<128><<<dim3(4, 4, 16), 256, SM128>>>(p);
    }
    k_softmax<<<NB * HH * NN, 256>>>();
    // AV: 512 batches (bn,h), M=512, N=64, K=512 -> oi hi
    {
        GemmP p = {attn_h, NN, (long long)NN * NN, vT_h, NN, (long long)DH * NN,
                   nullptr, oi_h, INNERD, (long long)NN * INNERD,
                   NN, nullptr, nullptr, 0, 1};
        k_mma<64><<<dim3(1, 4, BN_TOT * HH), 256, SM64>>>(p);
    }
    // final: M=32768, N=256, K=512 -> out fp32 (+bias)
    {
        GemmP p = {oi_h, INNERD, 0, woT_h, INNERD, 0,
                   out, nullptr, DIMC, 0,
                   INNERD, b_o, nullptr, 0, 0};
        k_mma<128><<<dim3(2, 256, 1), 256, SM128>>>(p);
    }
}

// round 17
// speedup vs baseline: 1.1059x; 1.1059x over previous
#include <cuda_runtime.h>
#include <cuda_bf16.h>
#include <cuda_fp16.h>
#include <float.h>
#include <math.h>
#include <stdint.h>

// Problem constants (fixed shapes)
#define BN_TOT 64      // b*r
#define NB 2           // b
#define RR 32          // r
#define NN 512         // n
#define DIMC 256       // DIM
#define HH 8           // heads
#define DH 64          // dim_head
#define INNERD 512     // HH*DH
#define KW 15          // conv kernel

// ---------------- scratch (device globals; no allocations allowed) ----------
__device__ float g_dots[NB * HH * NN * NN];         // logits fp32

// fp16 hi-only operands everywhere
__device__ uint16_t g_xs_h[BN_TOT * NN * DIMC];
__device__ uint16_t g_hdw_h[BN_TOT * NN * DIMC];
__device__ uint16_t g_pww_h[INNERD * DIMC];
__device__ uint16_t g_wkvT_h[2 * INNERD * DIMC];
__device__ uint16_t g_woT_h[DIMC * INNERD];
__device__ uint16_t g_vT_h[BN_TOT * INNERD * NN];
__device__ uint16_t g_attn_h[NB * HH * NN * NN];
__device__ uint16_t g_oi_h[BN_TOT * NN * INNERD];
__device__ uint16_t g_qr_h[NB * HH * NN * RR * DH];
__device__ uint16_t g_kr_h[NB * HH * NN * RR * DH];

__device__ unsigned char g_mask[BN_TOT * NN];
__device__ float g_has_rows[BN_TOT];
__device__ float g_m_any[NB * NN];
__device__ float g_alpha[NB];
__device__ float g_sin[NN * 32];
__device__ float g_cos[NN * 32];

// ========================= helpers ===========================================
__device__ __forceinline__ uint32_t smem_u32(const void* p) {
    uint32_t a;
    asm("{ .reg .u64 t; cvta.to.shared.u64 t, %1; cvt.u32.u64 %0, t; }" : "=r"(a) : "l"(p));
    return a;
}

#define LDSM4(r, addr)                                                          \
    asm volatile("ldmatrix.sync.aligned.m8n8.x4.shared.b16 {%0,%1,%2,%3}, [%4];" \
                 : "=r"((r)[0]), "=r"((r)[1]), "=r"((r)[2]), "=r"((r)[3])       \
                 : "r"(addr))

__device__ __forceinline__ void mma_h(float* c, const uint32_t* a, const uint32_t* b) {
    asm volatile("mma.sync.aligned.m16n8k16.row.col.f32.f16.f16.f32 "
                 "{%0,%1,%2,%3}, {%4,%5,%6,%7}, {%8,%9}, {%0,%1,%2,%3};"
                 : "+f"(c[0]), "+f"(c[1]), "+f"(c[2]), "+f"(c[3])
                 : "r"(a[0]), "r"(a[1]), "r"(a[2]), "r"(a[3]), "r"(b[0]), "r"(b[1]));
}

#define CP16(dst, src)                                                          \
    asm volatile("cp.async.cg.shared.global [%0], [%1], 16;" :: "r"(dst), "l"(src) : "memory")
#define CP_COMMIT() asm volatile("cp.async.commit_group;" ::: "memory")
#define CP_WAIT0()  asm volatile("cp.async.wait_group 0;" ::: "memory")

// byte offset in a 128B-per-row fp16 tile (64 k values/row), bank-swizzled
__device__ __forceinline__ uint32_t soff(int row, int kcol) {
    return (uint32_t)(row * 128 + ((kcol * 2) ^ ((row & 7) << 4)));
}

__device__ __forceinline__ uint16_t h16(float v) {
    return __half_as_ushort(__float2half_rn(v));
}

// ========================= fused prep (mask + trig), ONE block ===============
__global__ void __launch_bounds__(1024) k_prep(const void* mraw) {
    const unsigned char* mb = (const unsigned char*)mraw;
    int tid = threadIdx.x;
    __shared__ int s_high, s_odd;

    if (tid == 0) { s_high = 0; s_odd = 0; }
    __syncthreads();
    for (int idx = tid; idx < BN_TOT * NN; idx += 1024) {
        unsigned char v = mb[idx];
        if (v > 1) s_high = 1;
        if ((idx & 3) && v) s_odd = 1;
    }
    __syncthreads();
    int mode = s_high ? 2 : (s_odd ? 0 : 1);

    for (int idx = tid; idx < BN_TOT * NN; idx += 1024) {
        unsigned char v;
        if (mode == 0)      v = (mb[idx] != 0);
        else if (mode == 1) v = (((const int*)mraw)[idx] != 0);
        else                v = (((const float*)mraw)[idx] != 0.0f);
        g_mask[idx] = v;
    }
    __syncthreads();

    int w = tid >> 5, lane = tid & 31;
    for (int bb = 0; bb < 2; bb++) {
        int bn = w * 2 + bb;
        int any = 0;
        for (int q = lane; q < NN; q += 32) any |= g_mask[bn * NN + q];
        any = __any_sync(0xFFFFFFFFu, any);
        if (lane == 0) g_has_rows[bn] = (float)any;
    }
    __syncthreads();

    {
        int b = tid >> 9, i = tid & 511;
        int any = 0;
        for (int r = 0; r < RR; r++) any |= g_mask[(b * RR + r) * NN + i];
        g_m_any[b * NN + i] = (float)any;
        if (i == 0) {
            float s = 0.f;
            for (int r = 0; r < RR; r++) s += g_has_rows[b * RR + r];
            g_alpha[b] = (s > 0.f) ? 0.125f * rsqrtf(s) : 0.f;
        }
    }

    for (int idx = tid; idx < NN * 32; idx += 1024) {
        int i = idx >> 5, j = idx & 31;
        float inv = exp2f(-((float)(2 * j) / 64.0f) * 13.287712379549449f);
        float ang = (float)i * inv;
        g_sin[idx] = sinf(ang);
        g_cos[idx] = cosf(ang);
    }
}

// ====== fused weight transforms + depthwise conv (one launch, 2304 blocks) ===
// bid < 2048: weight transforms.  bid >= 2048: conv (256 blocks).
__global__ void __launch_bounds__(256) k_pre2(const float* __restrict__ pw_w,
                                              const float* __restrict__ w_kv,
                                              const float* __restrict__ w_o,
                                              const float* __restrict__ x,
                                              const float* __restrict__ dww,
                                              const float* __restrict__ dwb) {
    int bid = blockIdx.x;
    int t = threadIdx.x;
    if (bid < 512) {
        int i = bid * 256 + t;
        g_pww_h[i] = h16(pw_w[i]);
        return;
    }
    if (bid < 1536) {
        int i = (bid - 512) * 256 + t;
        int n = i >> 8, k = i & 255;
        g_wkvT_h[i] = h16(w_kv[k * 1024 + n]);
        return;
    }
    if (bid < 2048) {
        int i = (bid - 1536) * 256 + t;
        int n = i >> 9, k = i & 511;
        g_woT_h[i] = h16(w_o[k * 256 + n]);
        return;
    }
    // conv: also emits xs_h for free (win center == x[i])
    int cb = bid - 2048;
    int c = t;
    int bn = cb >> 2, seg = cb & 3;
    int i0 = seg * 128;
    float w[KW];
#pragma unroll
    for (int k = 0; k < KW; k++) w[k] = dww[c * KW + k];
    float bias = dwb[c];
    const float* xr = x + (size_t)bn * NN * DIMC + c;

    float win[KW];
#pragma unroll
    for (int k = 0; k < KW; k++) {
        int ii = i0 - KW / 2 + k;
        win[k] = (ii >= 0 && ii < NN) ? xr[(size_t)ii * DIMC] : 0.f;
    }
    uint16_t* oh = g_hdw_h + ((size_t)bn * NN + i0) * DIMC + c;
    uint16_t* ox = g_xs_h + ((size_t)bn * NN + i0) * DIMC + c;
    for (int i = i0; i < i0 + 128; i++) {
        float acc = bias;
#pragma unroll
        for (int k = 0; k < KW; k++) acc = fmaf(win[k], w[k], acc);
        *oh = h16(acc);
        *ox = h16(win[KW / 2]);
        oh += DIMC; ox += DIMC;
#pragma unroll
        for (int k = 0; k < KW - 1; k++) win[k] = win[k + 1];
        int ii = i + KW / 2 + 1;
        win[KW - 1] = (ii < NN) ? xr[(size_t)ii * DIMC] : 0.f;
    }
}

// ---------------- masked softmax (writes fp16 hi) ----------------------------
__global__ void k_softmax() {
    int row = blockIdx.x;
    int b = row >> 12;
    int i = row & 511;
    const float* p = g_dots + (size_t)row * NN;
    float rv = g_m_any[b * NN + i];
    int t = threadIdx.x;

    float m0 = g_m_any[b * NN + t];
    float m1 = g_m_any[b * NN + t + 256];
    float x0 = (rv != 0.f && m0 != 0.f) ? p[t]       : -FLT_MAX;
    float x1 = (rv != 0.f && m1 != 0.f) ? p[t + 256] : -FLT_MAX;

    __shared__ float red[256];
    float mx = fmaxf(x0, x1);
    red[t] = mx;
    __syncthreads();
    for (int s = 128; s > 0; s >>= 1) {
        if (t < s) red[t] = fmaxf(red[t], red[t + s]);
        __syncthreads();
    }
    mx = red[0];
    __syncthreads();
    float e0 = expf(x0 - mx), e1 = expf(x1 - mx);
    red[t] = e0 + e1;
    __syncthreads();
    for (int s = 128; s > 0; s >>= 1) {
        if (t < s) red[t] += red[t + s];
        __syncthreads();
    }
    float inv = 1.0f / red[0];
    size_t o = (size_t)row * NN;
    g_attn_h[o + t]       = h16(e0 * inv);
    g_attn_h[o + t + 256] = h16(e1 * inv);
}

// rotary epilogue: write fp16 hi-only q/k in (b,h,i,r*64+d) layout
__device__ __forceinline__ void rot_store(int row, int col, float ve, float vo,
                                          bool isq) {
    int i = row & 511, bn = row >> 9;
    int h = col >> 6, d = col & 63, j = d >> 1;
    float s = g_sin[i * 32 + j], c = g_cos[i * 32 + j];
    float oe = ve * c - vo * s;
    float oo = vo * c + ve * s;
    int b = bn >> 5, r = bn & 31;
    size_t dst = (((size_t)(b * HH + h) * NN + i) * (RR * DH)) + r * DH + d;
    if (isq) {
        float hr = g_has_rows[bn];
        oe *= hr; oo *= hr;
        *(uint32_t*)(g_qr_h + dst) = (uint32_t)h16(oe) | ((uint32_t)h16(oo) << 16);
    } else {
        *(uint32_t*)(g_kr_h + dst) = (uint32_t)h16(oe) | ((uint32_t)h16(oo) << 16);
    }
}

// ======= mma.sync fp16 NT GEMM, BK=64, 64x32 warp tiles, 2-stage (R13) =======
struct GemmP {
    const uint16_t *Ah; long long lda; long long a_bs;
    const uint16_t *Bh; long long ldb; long long b_bs;
    float* C;                                  // fp32 out (or null)
    uint16_t *Ch;                              // fp16 hi out (or null)
    long long ldc; long long c_bs;
    int K;
    const float* bias;
    const float* alpha_vec; int alpha_shift;
    int mode;   // 0 normal batch
    int emode;  // 0 plain, 6 merged proj (q/k rotary + v transpose)
};

template <int TN>
__global__ void __launch_bounds__(256) k_mma(GemmP p) {
    constexpr int NT8 = TN / 32;
    constexpr int NX4 = NT8 / 2;
    constexpr uint32_t SS = 16384u + TN * 128u;    // stage stride bytes (BK=64)
    extern __shared__ __align__(128) char dsm[];
    uint32_t sb = smem_u32(dsm);

    int tid = threadIdx.x, wid = tid >> 5, lane = tid & 31;
    int bx = blockIdx.x, by = blockIdx.y, z = blockIdx.z;

    const uint16_t* Ah;
    const uint16_t* Bh;
    size_t cbase = 0;
    if (p.emode == 6) {
        if (bx < 4)      { Ah = g_hdw_h; Bh = g_pww_h + (size_t)bx * 128 * DIMC; }
        else if (bx < 8) { Ah = g_xs_h;  Bh = g_wkvT_h + (size_t)(bx - 4) * 128 * DIMC; }
        else             { Ah = g_xs_h;  Bh = g_wkvT_h + (size_t)(512 + (bx - 8) * 128) * DIMC; }
        Ah += (size_t)by * 128 * DIMC;
    } else {
        size_t abase = (size_t)z * p.a_bs;
        size_t bbase = (size_t)z * p.b_bs + (size_t)bx * TN * p.ldb;
        cbase = (size_t)z * p.c_bs;
        abase += (size_t)by * 128 * p.lda;
        Ah = p.Ah + abase;
        Bh = p.Bh + bbase;
    }

    int m0 = (wid & 1) * 64;
    int n0 = (wid >> 1) * (TN / 4);
    int arow = m0 + (lane & 7) + ((lane >> 3) & 1) * 8;
    int akb  = ((lane >> 4) & 1) * 8;
    int brow = n0 + (lane & 7) + ((lane >> 4) & 1) * 8;
    int bkb  = ((lane >> 3) & 1) * 8;

    float acc[4][NT8][4];
#pragma unroll
    for (int i = 0; i < 4; i++)
#pragma unroll
        for (int j = 0; j < NT8; j++)
#pragma unroll
            for (int q = 0; q < 4; q++) acc[i][j][q] = 0.f;

    int KC = p.K >> 6;                     // BK = 64

    auto load_stage = [&](int st, int k0) {
        uint32_t base = sb + (uint32_t)st * SS;
#pragma unroll 4
        for (int idx = tid; idx < 1024; idx += 256) {
            int row = idx >> 3, c = idx & 7;
            uint32_t off = (uint32_t)(row * 128 + ((c * 16) ^ ((row & 7) << 4)));
            CP16(base + off, Ah + (size_t)row * p.lda + k0 + c * 8);
        }
#pragma unroll 4
        for (int idx = tid; idx < TN * 8; idx += 256) {
            int row = idx >> 3, c = idx & 7;
            uint32_t off = (uint32_t)(row * 128 + ((c * 16) ^ ((row & 7) << 4)));
            CP16(base + 16384 + off, Bh + (size_t)row * p.ldb + k0 + c * 8);
        }
    };

    load_stage(0, 0);
    CP_COMMIT();

    for (int ch = 0; ch < KC; ch++) {
        CP_WAIT0();
        __syncthreads();
        if (ch + 1 < KC) {
            load_stage((ch + 1) & 1, (ch + 1) << 6);
            CP_COMMIT();
        }

        uint32_t base = sb + (uint32_t)(ch & 1) * SS;
        uint32_t aHiB = base, bHiB = base + 16384;

#pragma unroll
        for (int kk = 0; kk < 64; kk += 16) {
            uint32_t ah[4][4];
#pragma unroll
            for (int mt = 0; mt < 4; mt++)
                LDSM4(ah[mt], aHiB + soff(arow + mt * 16, kk + akb));
            uint32_t bh[NX4][4];
#pragma unroll
            for (int nx = 0; nx < NX4; nx++)
                LDSM4(bh[nx], bHiB + soff(brow + nx * 16, kk + bkb));
#pragma unroll
            for (int mt = 0; mt < 4; mt++)
#pragma unroll
                for (int nt = 0; nt < NT8; nt++)
                    mma_h(acc[mt][nt], ah[mt], &bh[nt >> 1][(nt & 1) * 2]);
        }
    }

    // ---------------- epilogues ----------------
    int r0 = by * 128 + m0 + (lane >> 2);

    if (p.emode == 6) {
        if (bx >= 8) {
            // V: transpose 128x128 tile through smem -> vT_h
            __syncthreads();
            uint16_t* sm = (uint16_t*)dsm;     // 128*130*2 = 33280 B < 2*SS
            int rl0 = m0 + (lane >> 2);
            int cl0 = n0 + (lane & 3) * 2;
#pragma unroll
            for (int mt = 0; mt < 4; mt++)
#pragma unroll
                for (int nt = 0; nt < NT8; nt++) {
                    int rl = rl0 + mt * 16, cl = cl0 + nt * 8;
                    sm[(cl + 0) * 130 + rl]     = h16(acc[mt][nt][0]);
                    sm[(cl + 1) * 130 + rl]     = h16(acc[mt][nt][1]);
                    sm[(cl + 0) * 130 + rl + 8] = h16(acc[mt][nt][2]);
                    sm[(cl + 1) * 130 + rl + 8] = h16(acc[mt][nt][3]);
                }
            __syncthreads();
            int bn = by >> 2, i0g = (by & 3) * 128;
            int hd0 = (bx - 8) * 128;
            int c = tid >> 1, half = tid & 1;
            size_t dst = ((size_t)bn * 512 + hd0 + c) * 512 + i0g + half * 64;
            const uint16_t* srow = sm + c * 130 + half * 64;
#pragma unroll 4
            for (int r = 0; r < 64; r += 4) {
                uint2 val;
                val.x = (uint32_t)srow[r]     | ((uint32_t)srow[r + 1] << 16);
                val.y = (uint32_t)srow[r + 2] | ((uint32_t)srow[r + 3] << 16);
                *(uint2*)(g_vT_h + dst + r) = val;
            }
            return;
        }
        bool isq = (bx < 4);
        int c0l = (bx & 3) * 128 + n0 + (lane & 3) * 2;
#pragma unroll
        for (int mt = 0; mt < 4; mt++)
#pragma unroll
            for (int nt = 0; nt < NT8; nt++) {
                int row = r0 + mt * 16;
                int col = c0l + nt * 8;
                float b0 = 0.f, b1 = 0.f;
                if (isq) { b0 = p.bias[col]; b1 = p.bias[col + 1]; }
                rot_store(row, col, acc[mt][nt][0] + b0, acc[mt][nt][1] + b1, isq);
                rot_store(row + 8, col, acc[mt][nt][2] + b0, acc[mt][nt][3] + b1, isq);
            }
        return;
    }

    float alpha = p.alpha_vec ? p.alpha_vec[z >> p.alpha_shift] : 1.0f;
    int c0 = bx * TN + n0 + (lane & 3) * 2;
#pragma unroll
    for (int mt = 0; mt < 4; mt++) {
#pragma unroll
        for (int nt = 0; nt < NT8; nt++) {
            int row = r0 + mt * 16;
            int col = c0 + nt * 8;
            float b0 = 0.f, b1 = 0.f;
            if (p.bias) { b0 = p.bias[col]; b1 = p.bias[col + 1]; }
            float v00 = acc[mt][nt][0] * alpha + b0;
            float v01 = acc[mt][nt][1] * alpha + b1;
            float v10 = acc[mt][nt][2] * alpha + b0;
            float v11 = acc[mt][nt][3] * alpha + b1;
            if (p.C) {
                *(float2*)(p.C + cbase + (size_t)row * p.ldc + col) = make_float2(v00, v01);
                *(float2*)(p.C + cbase + (size_t)(row + 8) * p.ldc + col) = make_float2(v10, v11);
            }
            if (p.Ch) {
                *(uint32_t*)(p.Ch + cbase + (size_t)row * p.ldc + col) =
                    (uint32_t)h16(v00) | ((uint32_t)h16(v01) << 16);
                *(uint32_t*)(p.Ch + cbase + (size_t)(row + 8) * p.ldc + col) =
                    (uint32_t)h16(v10) | ((uint32_t)h16(v11) << 16);
            }
        }
    }
}

// ======= AV GEMM: block 256x64, warps 4x2 (64x32 tiles), BK=64, 2-stage ======
// grid (1, 2, 512): z = bn*8 + h.  C = oi_h (fp16), ldc = INNERD.
__global__ void __launch_bounds__(256) k_av() {
    constexpr uint32_t SS = 32768u + 8192u;    // A 256x64 + B 64x64 per stage
    extern __shared__ __align__(128) char dsm[];
    uint32_t sb = smem_u32(dsm);

    int tid = threadIdx.x, wid = tid >> 5, lane = tid & 31;
    int by = blockIdx.y, z = blockIdx.z;
    int bn = z >> 3, h = z & 7, b = bn >> 5;

    const uint16_t* Ah = g_attn_h + (size_t)(b * HH + h) * NN * NN + (size_t)by * 256 * NN;
    const uint16_t* Bh = g_vT_h + ((size_t)bn * 512 + h * 64) * NN;
    size_t cbase = (size_t)bn * NN * INNERD + h * 64;

    int mw = wid & 3, nw = wid >> 2;          // 4 m-warps x 2 n-warps
    int m0 = mw * 64, n0 = nw * 32;
    int arow = m0 + (lane & 7) + ((lane >> 3) & 1) * 8;
    int akb  = ((lane >> 4) & 1) * 8;
    int brow = n0 + (lane & 7) + ((lane >> 4) & 1) * 8;
    int bkb  = ((lane >> 3) & 1) * 8;

    float acc[4][4][4];
#pragma unroll
    for (int i = 0; i < 4; i++)
#pragma unroll
        for (int j = 0; j < 4; j++)
#pragma unroll
            for (int q = 0; q < 4; q++) acc[i][j][q] = 0.f;

    auto load_stage = [&](int st, int k0) {
        uint32_t base = sb + (uint32_t)st * SS;
#pragma unroll 8
        for (int idx = tid; idx < 2048; idx += 256) {       // A: 256 rows x 8 c
            int row = idx >> 3, c = idx & 7;
            uint32_t off = (uint32_t)(row * 128 + ((c * 16) ^ ((row & 7) << 4)));
            CP16(base + off, Ah + (size_t)row * NN + k0 + c * 8);
        }
#pragma unroll 2
        for (int idx = tid; idx < 512; idx += 256) {        // B: 64 rows x 8 c
            int row = idx >> 3, c = idx & 7;
            uint32_t off = (uint32_t)(row * 128 + ((c * 16) ^ ((row & 7) << 4)));
            CP16(base + 32768 + off, Bh + (size_t)row * NN + k0 + c * 8);
        }
    };

    load_stage(0, 0);
    CP_COMMIT();

    for (int ch = 0; ch < 8; ch++) {                        // K = 512
        CP_WAIT0();
        __syncthreads();
        if (ch + 1 < 8) {
            load_stage((ch + 1) & 1, (ch + 1) << 6);
            CP_COMMIT();
        }

        uint32_t base = sb + (uint32_t)(ch & 1) * SS;
        uint32_t aHiB = base, bHiB = base + 32768;

#pragma unroll
        for (int kk = 0; kk < 64; kk += 16) {
            uint32_t ah[4][4];
#pragma unroll
            for (int mt = 0; mt < 4; mt++)
                LDSM4(ah[mt], aHiB + soff(arow + mt * 16, kk + akb));
            uint32_t bh[2][4];
#pragma unroll
            for (int nx = 0; nx < 2; nx++)
                LDSM4(bh[nx], bHiB + soff(brow + nx * 16, kk + bkb));
#pragma unroll
            for (int mt = 0; mt < 4; mt++)
#pragma unroll
                for (int nt = 0; nt < 4; nt++)
                    mma_h(acc[mt][nt], ah[mt], &bh[nt >> 1][(nt & 1) * 2]);
        }
    }

    // epilogue: fp16 hi out
    int r0 = by * 256 + m0 + (lane >> 2);
    int c0 = n0 + (lane & 3) * 2;
#pragma unroll
    for (int mt = 0; mt < 4; mt++) {
#pragma unroll
        for (int nt = 0; nt < 4; nt++) {
            int row = r0 + mt * 16;
            int col = c0 + nt * 8;
            *(uint32_t*)(g_oi_h + cbase + (size_t)row * INNERD + col) =
                (uint32_t)h16(acc[mt][nt][0]) | ((uint32_t)h16(acc[mt][nt][1]) << 16);
            *(uint32_t*)(g_oi_h + cbase + (size_t)(row + 8) * INNERD + col) =
                (uint32_t)h16(acc[mt][nt][2]) | ((uint32_t)h16(acc[mt][nt][3]) << 16);
        }
    }
}

// ---------------- launch -----------------------------------------------------
#define SYM(var, sym) decltype(&sym[0]) var; cudaGetSymbolAddress((void**)&var, sym)

extern "C" void kernel_launch(void* const* d_in, const int* in_sizes, int n_in,
                              void* d_out, int out_size) {
    const float* x    = (const float*)d_in[0];
    const void*  mask = d_in[1];
    const float* dw_w = (const float*)d_in[3];
    const float* dw_b = (const float*)d_in[4];
    const float* pw_w = (const float*)d_in[5];
    const float* pw_b = (const float*)d_in[6];
    const float* w_kv = (const float*)d_in[7];
    const float* w_o  = (const float*)d_in[8];
    const float* b_o  = (const float*)d_in[9];
    float* out = (float*)d_out;

    const int SM128 = 2 * (16384 + 128 * 128);   // 65536
    const int SMAV  = 2 * (32768 + 8192);        // 81920
    cudaFuncSetAttribute(k_mma<128>, cudaFuncAttributeMaxDynamicSharedMemorySize, SM128);
    cudaFuncSetAttribute(k_av,       cudaFuncAttributeMaxDynamicSharedMemorySize, SMAV);

    SYM(dots_p, g_dots);
    SYM(qr_h, g_qr_h);
    SYM(kr_h, g_kr_h);
    SYM(oi_h, g_oi_h);
    SYM(woT_h, g_woT_h);
    SYM(alpha_p, g_alpha);

    k_prep<<<1, 1024>>>(mask);
    k_pre2<<<2304, 256>>>(pw_w, w_kv, w_o, x, dw_w, dw_b);

    // merged projections: q (bias+rotary+has_rows), k (rotary), v (transpose->vT)
    {
        GemmP p = {nullptr, DIMC, 0, nullptr, DIMC, 0,
                   nullptr, nullptr, 0, 0,
                   DIMC, pw_b, nullptr, 0, 0, 6};
        k_mma<128><<<dim3(12, 256, 1), 256, SM128>>>(p);
    }
    // dots: 16 batches, M=N=512, K=2048 -> fp32 (alpha per b)
    {
        GemmP p = {qr_h, 2048, (long long)NN * 2048, kr_h, 2048, (long long)NN * 2048,
                   dots_p, nullptr, NN, (long long)NN * NN,
                   2048, nullptr, alpha_p, 3, 0, 0};
        k_mma<128><<<dim3(4, 4, 16), 256, SM128>>>(p);
    }
    k_softmax<<<NB * HH * NN, 256>>>();
    // AV: block 256x64, grid (1, 2, 512) -> oi hi
    k_av<<<dim3(1, 2, 512), 256, SMAV>>>();
    // final: M=32768, N=256, K=512 -> out fp32 (+bias)
    {
        GemmP p = {oi_h, INNERD, 0, woT_h, INNERD, 0,
                   out, nullptr, DIMC, 0,
                   INNERD, b_o, nullptr, 0, 0, 0};
        k_mma<128><<<dim3(2, 256, 1), 256, SM128>>>(p);
    }
}